// round 2
// baseline (speedup 1.0000x reference)
#include <cuda_runtime.h>
#include <cuda_bf16.h>

constexpr int Bn = 4096;
constexpr int Tn = 4096;
constexpr int NC = 32;           // chunks per row
constexpr int Tc = Tn / NC;      // 128 steps per chunk
constexpr int NG4 = Tc / 4;      // float4 groups per chunk

__device__ float d_A[NC * Bn];
__device__ float d_L[NC * Bn];
__device__ float d_H[NC * Bn];
__device__ float d_S[NC * Bn];

__device__ __forceinline__ void compose_step(
    float ga, float pa, float pp, float& A, float& L, float& H)
{
    const float C  = 13.5f;
    const float K  = 5.0f / 60.0f;
    const float RK = 5.0f * (5.0f / 60.0f);

    float p   = fminf(fmaxf(pa * pp, 0.0f), 5.0f) * K;
    float glK = fmaxf(ga * 5.0f, -5.0f) * K;
    float a   = fminf(p + glK, RK);
    float h   = C + fminf(glK, 0.0f);

    A = A + a;
    L = fmaxf(L + a, 0.0f);
    H = fminf(fmaxf(H + a, 0.0f), h);
}

// ── K1: per-(row,chunk) compose the chunk's clamp function ──────────────
__global__ void __launch_bounds__(256) compose_kernel(
    const float* __restrict__ g_ga, const float* __restrict__ g_pa,
    const float* __restrict__ g_pp)
{
    const int tid = blockIdx.x * 256 + threadIdx.x;     // [0, Bn*NC)
    const int b = tid & (Bn - 1);
    const int c = tid >> 12;                            // Bn = 2^12

    const size_t off = (size_t)b * Tn + (size_t)c * Tc;
    const float4* gaR = reinterpret_cast<const float4*>(g_ga + off);
    const float4* paR = reinterpret_cast<const float4*>(g_pa + off);
    const float4* ppR = reinterpret_cast<const float4*>(g_pp + off);

    // identity on the state domain [0, C]: clamp(s, 0, C) == s
    float A = 0.0f, L = 0.0f, H = 13.5f;

#pragma unroll 4
    for (int i = 0; i < NG4; ++i) {
        const float4 vga = gaR[i];
        const float4 vpa = paR[i];
        const float4 vpp = ppR[i];
        compose_step(vga.x, vpa.x, vpp.x, A, L, H);
        compose_step(vga.y, vpa.y, vpp.y, A, L, H);
        compose_step(vga.z, vpa.z, vpp.z, A, L, H);
        compose_step(vga.w, vpa.w, vpp.w, A, L, H);
    }

    d_A[c * Bn + b] = A;
    d_L[c * Bn + b] = L;
    d_H[c * Bn + b] = H;
}

// ── K2: per-row sequential scan over the NC chunk functions ─────────────
__global__ void __launch_bounds__(256) chunkscan_kernel()
{
    const int b = blockIdx.x * 256 + threadIdx.x;       // [0, Bn)
    float s = 6.75f;
#pragma unroll
    for (int c = 0; c < NC; ++c) {
        d_S[c * Bn + b] = s;
        const float A = d_A[c * Bn + b];
        const float L = d_L[c * Bn + b];
        const float H = d_H[c * Bn + b];
        s = fminf(fmaxf(s + A, L), H);
    }
}

// ── K3: replay exact per-step recurrence from chunk-start state ─────────
__device__ __forceinline__ float battery_step(
    float s, float ga, float pa, float pp, float pr,
    float& cost_out, float& trace_out)
{
    const float C = 13.5f;
    const float K = 5.0f / 60.0f;
    const float R = 5.0f;

    float rp  = fminf(fmaxf(pa * pp, 0.0f), R);
    float p   = rp * K;
    float gl  = fmaxf(ga * R, -R);
    float pvk = pp * K;
    float prc = pr * 1.0e-3f;

    float after_pv = fminf(s + p, C);
    float amt      = after_pv - s;
    float hi       = R - amt * 12.0f;
    float rgr      = fminf(gl, hi);
    float ns       = fminf(fmaxf(after_pv + rgr * K, 0.0f), C);

    float grid_amt  = ns - after_pv;
    float pv_export = amt - pvk;
    cost_out  = prc * (grid_amt + pv_export);
    trace_out = ns;
    return ns;
}

__global__ void __launch_bounds__(256) replay_kernel(
    const float* __restrict__ g_ga, const float* __restrict__ g_pa,
    const float* __restrict__ g_pp, const float* __restrict__ g_pr,
    float* __restrict__ g_trace, float* __restrict__ g_cost)
{
    const int tid = blockIdx.x * 256 + threadIdx.x;
    const int b = tid & (Bn - 1);
    const int c = tid >> 12;

    const size_t off = (size_t)b * Tn + (size_t)c * Tc;
    const float4* gaR = reinterpret_cast<const float4*>(g_ga + off);
    const float4* paR = reinterpret_cast<const float4*>(g_pa + off);
    const float4* ppR = reinterpret_cast<const float4*>(g_pp + off);
    const float4* prR = reinterpret_cast<const float4*>(g_pr + off);

    float*  trR = g_trace + (size_t)b * (Tn + 1) + (size_t)c * Tc;
    float4* coR = reinterpret_cast<float4*>(g_cost + off);

    float s = d_S[c * Bn + b];
    if (c == 0) trR[0] = 6.75f;

#pragma unroll 4
    for (int i = 0; i < NG4; ++i) {
        const float4 vga = gaR[i];
        const float4 vpa = paR[i];
        const float4 vpp = ppR[i];
        const float4 vpr = prR[i];

        float4 cst;
        float tr0, tr1, tr2, tr3;
        s = battery_step(s, vga.x, vpa.x, vpp.x, vpr.x, cst.x, tr0);
        s = battery_step(s, vga.y, vpa.y, vpp.y, vpr.y, cst.y, tr1);
        s = battery_step(s, vga.z, vpa.z, vpp.z, vpr.z, cst.z, tr2);
        s = battery_step(s, vga.w, vpa.w, vpp.w, vpr.w, cst.w, tr3);

        trR[4 * i + 1] = tr0;
        trR[4 * i + 2] = tr1;
        trR[4 * i + 3] = tr2;
        trR[4 * i + 4] = tr3;
        coR[i] = cst;
    }
}

extern "C" void kernel_launch(void* const* d_in, const int* in_sizes, int n_in,
                              void* d_out, int out_size)
{
    const float* ga = (const float*)d_in[0];
    const float* pa = (const float*)d_in[1];
    const float* pp = (const float*)d_in[2];
    const float* pr = (const float*)d_in[3];

    float* out   = (float*)d_out;
    float* trace = out;                               // [B, T+1]
    float* cost  = out + (size_t)Bn * (Tn + 1);       // [B, T]

    compose_kernel<<<(Bn * NC) / 256, 256>>>(ga, pa, pp);
    chunkscan_kernel<<<Bn / 256, 256>>>();
    replay_kernel<<<(Bn * NC) / 256, 256>>>(ga, pa, pp, pr, trace, cost);
}

// round 5
// speedup vs baseline: 1.1373x; 1.1373x over previous
#include <cuda_runtime.h>
#include <cuda_bf16.h>

constexpr int Bn  = 4096;
constexpr int Tn  = 4096;
constexpr int NC  = 64;          // chunks per row
constexpr int Tc  = Tn / NC;     // 64 steps per chunk
constexpr int NG4 = Tc / 4;      // 16 float4 groups per chunk

__device__ float d_A[NC * Bn];
__device__ float d_L[NC * Bn];
__device__ float d_H[NC * Bn];
__device__ float d_S[NC * Bn];

// ── step map as a clamp function: s -> min(max(s + a, L), H) ────────────
__device__ __forceinline__ void compose_step(
    float ga, float pa, float pp, float& A, float& L, float& H)
{
    const float C  = 13.5f;
    const float K  = 5.0f / 60.0f;
    const float RK = 5.0f * (5.0f / 60.0f);

    float p   = fminf(fmaxf(pa * pp, 0.0f), 5.0f) * K;
    float glK = fmaxf(ga * 5.0f, -5.0f) * K;
    float a   = fminf(p + glK, RK);
    float h   = C + fminf(glK, 0.0f);

    A = A + a;
    L = fmaxf(L + a, 0.0f);
    H = fminf(fmaxf(H + a, 0.0f), h);
}

// ── K1: per-(row,chunk) compose the chunk's clamp function ──────────────
__global__ void __launch_bounds__(256) compose_kernel(
    const float* __restrict__ g_ga, const float* __restrict__ g_pa,
    const float* __restrict__ g_pp)
{
    const int tid = blockIdx.x * 256 + threadIdx.x;     // [0, Bn*NC)
    const int b = tid & (Bn - 1);
    const int c = tid >> 12;

    const size_t off = (size_t)b * Tn + (size_t)c * Tc;
    const float4* gaR = reinterpret_cast<const float4*>(g_ga + off);
    const float4* paR = reinterpret_cast<const float4*>(g_pa + off);
    const float4* ppR = reinterpret_cast<const float4*>(g_pp + off);

    float A = 0.0f, L = 0.0f, H = 13.5f;   // identity on [0, C]

#pragma unroll 4
    for (int i = 0; i < NG4; ++i) {
        const float4 vga = gaR[i];
        const float4 vpa = paR[i];
        const float4 vpp = ppR[i];
        compose_step(vga.x, vpa.x, vpp.x, A, L, H);
        compose_step(vga.y, vpa.y, vpp.y, A, L, H);
        compose_step(vga.z, vpa.z, vpp.z, A, L, H);
        compose_step(vga.w, vpa.w, vpp.w, A, L, H);
    }

    d_A[c * Bn + b] = A;
    d_L[c * Bn + b] = L;
    d_H[c * Bn + b] = H;
}

// ── K2: per-row sequential scan over the NC chunk functions ─────────────
__global__ void __launch_bounds__(256) chunkscan_kernel()
{
    const int b = blockIdx.x * 256 + threadIdx.x;       // [0, Bn)
    float s = 6.75f;
#pragma unroll 8
    for (int c = 0; c < NC; ++c) {
        d_S[c * Bn + b] = s;
        const float A = d_A[c * Bn + b];
        const float L = d_L[c * Bn + b];
        const float H = d_H[c * Bn + b];
        s = fminf(fmaxf(s + A, L), H);
    }
}

// ── K3: replay exact per-step recurrence from chunk-start state ─────────
__device__ __forceinline__ float battery_step(
    float s, float ga, float pa, float pp, float pr,
    float& cost_out, float& trace_out)
{
    const float C = 13.5f;
    const float K = 5.0f / 60.0f;
    const float R = 5.0f;

    float rp  = fminf(fmaxf(pa * pp, 0.0f), R);
    float p   = rp * K;
    float gl  = fmaxf(ga * R, -R);
    float pvk = pp * K;
    float prc = pr * 1.0e-3f;

    float after_pv = fminf(s + p, C);
    float amt      = after_pv - s;
    float hi       = R - amt * 12.0f;
    float rgr      = fminf(gl, hi);
    float ns       = fminf(fmaxf(after_pv + rgr * K, 0.0f), C);

    float grid_amt  = ns - after_pv;
    float pv_export = amt - pvk;
    cost_out  = prc * (grid_amt + pv_export);
    trace_out = ns;
    return ns;
}

__global__ void __launch_bounds__(256) replay_kernel(
    const float* __restrict__ g_ga, const float* __restrict__ g_pa,
    const float* __restrict__ g_pp, const float* __restrict__ g_pr,
    float* __restrict__ g_trace, float* __restrict__ g_cost)
{
    // per-warp trace tile: 32 rows x 32 steps, padded to 33 (conflict-free)
    __shared__ float tr_tile[8][32][33];

    const int tid  = blockIdx.x * 256 + threadIdx.x;
    const int b    = tid & (Bn - 1);
    const int c    = tid >> 12;                 // same c for entire block
    const int lane = threadIdx.x & 31;
    const int w    = threadIdx.x >> 5;

    const size_t off = (size_t)b * Tn + (size_t)c * Tc;
    const float4* gaR = reinterpret_cast<const float4*>(g_ga + off);
    const float4* paR = reinterpret_cast<const float4*>(g_pa + off);
    const float4* ppR = reinterpret_cast<const float4*>(g_pp + off);
    const float4* prR = reinterpret_cast<const float4*>(g_pr + off);
    float4* coR = reinterpret_cast<float4*>(g_cost + off);

    float s = d_S[c * Bn + b];
    if (c == 0) g_trace[(size_t)b * (Tn + 1)] = 6.75f;

    // warp-base row for the coalesced flush
    const int bBase = ((blockIdx.x * 256) & (Bn - 1)) + w * 32;
    float* flush_base = g_trace + (size_t)bBase * (Tn + 1) + (size_t)c * Tc + 1;

#pragma unroll
    for (int half = 0; half < 2; ++half) {
#pragma unroll
        for (int g = 0; g < 8; ++g) {
            const int i = half * 8 + g;
            const float4 vga = gaR[i];
            const float4 vpa = paR[i];
            const float4 vpp = ppR[i];
            const float4 vpr = prR[i];

            float4 cst;
            float tr0, tr1, tr2, tr3;
            s = battery_step(s, vga.x, vpa.x, vpp.x, vpr.x, cst.x, tr0);
            s = battery_step(s, vga.y, vpa.y, vpp.y, vpr.y, cst.y, tr1);
            s = battery_step(s, vga.z, vpa.z, vpp.z, vpr.z, cst.z, tr2);
            s = battery_step(s, vga.w, vpa.w, vpp.w, vpr.w, cst.w, tr3);

            tr_tile[w][lane][4 * g + 0] = tr0;
            tr_tile[w][lane][4 * g + 1] = tr1;
            tr_tile[w][lane][4 * g + 2] = tr2;
            tr_tile[w][lane][4 * g + 3] = tr3;
            coR[i] = cst;
        }
        __syncwarp();
        // coalesced flush: each iteration writes 128 contiguous bytes per warp
        float* fb = flush_base + half * 32;
#pragma unroll 8
        for (int r = 0; r < 32; ++r) {
            fb[(size_t)r * (Tn + 1) + lane] = tr_tile[w][r][lane];
        }
        __syncwarp();
    }
}

extern "C" void kernel_launch(void* const* d_in, const int* in_sizes, int n_in,
                              void* d_out, int out_size)
{
    const float* ga = (const float*)d_in[0];
    const float* pa = (const float*)d_in[1];
    const float* pp = (const float*)d_in[2];
    const float* pr = (const float*)d_in[3];

    float* out   = (float*)d_out;
    float* trace = out;                               // [B, T+1]
    float* cost  = out + (size_t)Bn * (Tn + 1);       // [B, T]

    compose_kernel<<<(Bn * NC) / 256, 256>>>(ga, pa, pp);
    chunkscan_kernel<<<Bn / 256, 256>>>();
    replay_kernel<<<(Bn * NC) / 256, 256>>>(ga, pa, pp, pr, trace, cost);
}

// round 7
// speedup vs baseline: 1.5150x; 1.3321x over previous
#include <cuda_runtime.h>
#include <cuda_bf16.h>

constexpr int Bn  = 4096;
constexpr int Tn  = 4096;
constexpr int NC  = 64;           // chunks per row
constexpr int Tc  = Tn / NC;      // 64 steps per chunk
constexpr int SL  = 16;           // steps per slice
constexpr int NSL = Tc / SL;      // 4 slices per chunk
constexpr int RPB = 128;          // rows per block (= threads per block)
constexpr int PAD = 130;          // smem row stride in words (130 % 32 == 2)

__device__ float d_A[NC * Bn];
__device__ float d_L[NC * Bn];
__device__ float d_H[NC * Bn];
__device__ float d_S[NC * Bn];

// step map as clamp: s -> min(max(s + a, L), H)
__device__ __forceinline__ void compose_step(
    float ga, float pa, float pp, float& A, float& L, float& H)
{
    const float C  = 13.5f;
    const float K  = 5.0f / 60.0f;
    const float RK = 5.0f * K;

    float p   = fminf(fmaxf(pa * pp, 0.0f), 5.0f) * K;
    float glK = fmaxf(ga * 5.0f, -5.0f) * K;
    float a   = fminf(p + glK, RK);
    float h   = C + fminf(glK, 0.0f);

    A = A + a;
    L = fmaxf(L + a, 0.0f);
    H = fminf(fmaxf(H + a, 0.0f), h);
}

__device__ __forceinline__ float battery_step(
    float s, float ga, float pa, float pp, float pr,
    float& cost_out, float& trace_out)
{
    const float C = 13.5f;
    const float K = 5.0f / 60.0f;
    const float R = 5.0f;

    float rp  = fminf(fmaxf(pa * pp, 0.0f), R);
    float p   = rp * K;
    float gl  = fmaxf(ga * R, -R);
    float pvk = pp * K;
    float prc = pr * 1.0e-3f;

    float after_pv = fminf(s + p, C);
    float amt      = after_pv - s;
    float hi       = R - amt * 12.0f;
    float rgr      = fminf(gl, hi);
    float ns       = fminf(fmaxf(after_pv + rgr * K, 0.0f), C);

    float grid_amt  = ns - after_pv;
    float pv_export = amt - pvk;
    cost_out  = prc * (grid_amt + pv_export);
    trace_out = ns;
    return ns;
}

// stage one array's [128 rows x 64B] slice into time-major smem [SL][PAD]
__device__ __forceinline__ void stage_slice(
    const float* __restrict__ g, size_t slice_base, int tq, int rophase,
    float* __restrict__ sm)
{
#pragma unroll
    for (int p = 0; p < 4; ++p) {
        const int row = p * 32 + rophase;
        const float4 v = *reinterpret_cast<const float4*>(
            g + slice_base + (size_t)row * Tn + tq * 4);
        sm[(tq * 4 + 0) * PAD + row] = v.x;
        sm[(tq * 4 + 1) * PAD + row] = v.y;
        sm[(tq * 4 + 2) * PAD + row] = v.z;
        sm[(tq * 4 + 3) * PAD + row] = v.w;
    }
}

// ── K1: compose chunk clamp functions, fully coalesced via smem ─────────
__global__ void __launch_bounds__(RPB) compose_kernel(
    const float* __restrict__ g_ga, const float* __restrict__ g_pa,
    const float* __restrict__ g_pp)
{
    __shared__ float sGA[SL * PAD], sPA[SL * PAD], sPP[SL * PAD];

    const int t  = threadIdx.x;
    const int b0 = (blockIdx.x & 31) * RPB;
    const int c  = blockIdx.x >> 5;
    const int b  = b0 + t;

    const int tq      = t & 3;
    const int rophase = t >> 2;

    const size_t base = (size_t)b0 * Tn + (size_t)c * Tc;

    float A = 0.0f, L = 0.0f, H = 13.5f;   // identity on [0, C]

    for (int sl = 0; sl < NSL; ++sl) {
        const size_t soff = base + sl * SL;
        stage_slice(g_ga, soff, tq, rophase, sGA);
        stage_slice(g_pa, soff, tq, rophase, sPA);
        stage_slice(g_pp, soff, tq, rophase, sPP);
        __syncthreads();
#pragma unroll
        for (int tt = 0; tt < SL; ++tt) {
            compose_step(sGA[tt * PAD + t], sPA[tt * PAD + t],
                         sPP[tt * PAD + t], A, L, H);
        }
        __syncthreads();
    }

    d_A[c * Bn + b] = A;
    d_L[c * Bn + b] = L;
    d_H[c * Bn + b] = H;
}

// ── K2: per-row sequential scan over chunk functions ────────────────────
__global__ void __launch_bounds__(256) chunkscan_kernel()
{
    const int b = blockIdx.x * 256 + threadIdx.x;
    float s = 6.75f;
#pragma unroll 8
    for (int c = 0; c < NC; ++c) {
        d_S[c * Bn + b] = s;
        const float A = d_A[c * Bn + b];
        const float L = d_L[c * Bn + b];
        const float H = d_H[c * Bn + b];
        s = fminf(fmaxf(s + A, L), H);
    }
}

// ── K3: replay from chunk-start states; all I/O coalesced via smem ──────
__global__ void __launch_bounds__(RPB) replay_kernel(
    const float* __restrict__ g_ga, const float* __restrict__ g_pa,
    const float* __restrict__ g_pp, const float* __restrict__ g_pr,
    float* __restrict__ g_trace, float* __restrict__ g_cost)
{
    __shared__ float sGA[SL * PAD], sPA[SL * PAD], sPP[SL * PAD], sPR[SL * PAD];

    const int t  = threadIdx.x;
    const int b0 = (blockIdx.x & 31) * RPB;
    const int c  = blockIdx.x >> 5;
    const int b  = b0 + t;

    const int tq      = t & 3;
    const int rophase = t >> 2;
    const int w       = t >> 5;
    const int lane    = t & 31;
    const int l16     = lane & 15;
    const int rh      = lane >> 4;

    const size_t base = (size_t)b0 * Tn + (size_t)c * Tc;

    float s = d_S[c * Bn + b];
    if (c == 0) g_trace[(size_t)b * (Tn + 1)] = 6.75f;

    for (int sl = 0; sl < NSL; ++sl) {
        const size_t soff = base + sl * SL;
        stage_slice(g_ga, soff, tq, rophase, sGA);
        stage_slice(g_pa, soff, tq, rophase, sPA);
        stage_slice(g_pp, soff, tq, rophase, sPP);
        stage_slice(g_pr, soff, tq, rophase, sPR);
        __syncthreads();

        // scan 16 steps; write trace into sGA, cost into sPR (in place)
#pragma unroll
        for (int tt = 0; tt < SL; ++tt) {
            float cost, tr;
            s = battery_step(s, sGA[tt * PAD + t], sPA[tt * PAD + t],
                             sPP[tt * PAD + t], sPR[tt * PAD + t], cost, tr);
            sGA[tt * PAD + t] = tr;
            sPR[tt * PAD + t] = cost;
        }
        __syncthreads();

        // flush: warp w owns rows [w*32, w*32+32); 2 rows per iteration
        const int tcol = c * Tc + sl * SL;
#pragma unroll
        for (int rr = 0; rr < 32; rr += 2) {
            const int r = w * 32 + rr + rh;
            const float trv = sGA[l16 * PAD + r];
            const float cov = sPR[l16 * PAD + r];
            g_trace[(size_t)(b0 + r) * (Tn + 1) + tcol + 1 + l16] = trv;
            g_cost [(size_t)(b0 + r) * Tn       + tcol + l16]     = cov;
        }
        __syncthreads();
    }
}

extern "C" void kernel_launch(void* const* d_in, const int* in_sizes, int n_in,
                              void* d_out, int out_size)
{
    const float* ga = (const float*)d_in[0];
    const float* pa = (const float*)d_in[1];
    const float* pp = (const float*)d_in[2];
    const float* pr = (const float*)d_in[3];

    float* out   = (float*)d_out;
    float* trace = out;                               // [B, T+1]
    float* cost  = out + (size_t)Bn * (Tn + 1);       // [B, T]

    const int nblk = (Bn * NC) / RPB;                 // 2048
    compose_kernel<<<nblk, RPB>>>(ga, pa, pp);
    chunkscan_kernel<<<Bn / 256, 256>>>();
    replay_kernel<<<nblk, RPB>>>(ga, pa, pp, pr, trace, cost);
}

// round 8
// speedup vs baseline: 1.8400x; 1.2145x over previous
#include <cuda_runtime.h>
#include <cuda_bf16.h>

constexpr int Bn  = 4096;
constexpr int Tn  = 4096;
constexpr int NC  = 64;           // chunks per row
constexpr int Tc  = Tn / NC;      // 64 steps per chunk
constexpr int SL  = 16;           // steps per slice
constexpr int NSL = Tc / SL;      // 4 slices per chunk
constexpr int RPB = 128;          // rows per block (= threads per block)
constexpr int PAD = 130;          // smem row stride in words
constexpr int NRG = Bn / RPB;     // 32 row-groups

__device__ float d_A[NC * Bn];    // chunk aggregate: shift
__device__ float d_L[NC * Bn];    // chunk aggregate: lower clamp
__device__ float d_H[NC * Bn];    // chunk aggregate: upper clamp
__device__ float d_S[NC * Bn];    // chunk END state (inclusive)
__device__ int   d_flag[NC * NRG];// 0 = none, 1 = aggregate, 2 = inclusive

// step map as clamp: s -> min(max(s + a, L), H)
__device__ __forceinline__ void compose_step(
    float ga, float pa, float pp, float& A, float& L, float& H)
{
    const float K  = 5.0f / 60.0f;
    const float RK = 5.0f * K;

    float p   = fminf(fmaxf(pa * pp, 0.0f), 5.0f) * K;
    float glK = fmaxf(ga * 5.0f, -5.0f) * K;
    float a   = fminf(p + glK, RK);
    float h   = 13.5f + fminf(glK, 0.0f);

    A = A + a;
    L = fmaxf(L + a, 0.0f);
    H = fminf(fmaxf(H + a, 0.0f), h);
}

__device__ __forceinline__ float battery_step(
    float s, float ga, float pa, float pp, float pr,
    float& cost_out, float& trace_out)
{
    const float C = 13.5f;
    const float K = 5.0f / 60.0f;
    const float R = 5.0f;

    float rp  = fminf(fmaxf(pa * pp, 0.0f), R);
    float p   = rp * K;
    float gl  = fmaxf(ga * R, -R);
    float pvk = pp * K;
    float prc = pr * 1.0e-3f;

    float after_pv = fminf(s + p, C);
    float amt      = after_pv - s;
    float hi       = R - amt * 12.0f;
    float rgr      = fminf(gl, hi);
    float ns       = fminf(fmaxf(after_pv + rgr * K, 0.0f), C);

    float grid_amt  = ns - after_pv;
    float pv_export = amt - pvk;
    cost_out  = prc * (grid_amt + pv_export);
    trace_out = ns;
    return ns;
}

// stage one array's [128 rows x 64B] slice into time-major smem [SL][PAD]
__device__ __forceinline__ void stage_slice(
    const float* __restrict__ g, size_t slice_base, int tq, int rophase,
    float* __restrict__ sm)
{
#pragma unroll
    for (int p = 0; p < 4; ++p) {
        const int row = p * 32 + rophase;
        const float4 v = *reinterpret_cast<const float4*>(
            g + slice_base + (size_t)row * Tn + tq * 4);
        sm[(tq * 4 + 0) * PAD + row] = v.x;
        sm[(tq * 4 + 1) * PAD + row] = v.y;
        sm[(tq * 4 + 2) * PAD + row] = v.z;
        sm[(tq * 4 + 3) * PAD + row] = v.w;
    }
}

__global__ void __launch_bounds__(256) reset_flags_kernel()
{
    const int i = blockIdx.x * 256 + threadIdx.x;
    if (i < NC * NRG) d_flag[i] = 0;
}

__global__ void __launch_bounds__(RPB) fused_kernel(
    const float* __restrict__ g_ga, const float* __restrict__ g_pa,
    const float* __restrict__ g_pp, const float* __restrict__ g_pr,
    float* __restrict__ g_trace, float* __restrict__ g_cost)
{
    __shared__ float sGA[SL * PAD], sPA[SL * PAD], sPP[SL * PAD], sPR[SL * PAD];
    __shared__ int s_flag;

    const int t  = threadIdx.x;
    const int rg = blockIdx.x & (NRG - 1);
    const int c  = blockIdx.x >> 5;
    const int b0 = rg * RPB;
    const int b  = b0 + t;

    const int tq      = t & 3;
    const int rophase = t >> 2;
    const int w       = t >> 5;
    const int lane    = t & 31;
    const int l16     = lane & 15;
    const int rh      = lane >> 4;

    const size_t base = (size_t)b0 * Tn + (size_t)c * Tc;

    // ── Phase A: compose this chunk's clamp function ────────────────────
    float A = 0.0f, L = 0.0f, H = 13.5f;   // identity on [0, C]
    for (int sl = 0; sl < NSL; ++sl) {
        const size_t soff = base + sl * SL;
        stage_slice(g_ga, soff, tq, rophase, sGA);
        stage_slice(g_pa, soff, tq, rophase, sPA);
        stage_slice(g_pp, soff, tq, rophase, sPP);
        __syncthreads();
#pragma unroll
        for (int tt = 0; tt < SL; ++tt)
            compose_step(sGA[tt * PAD + t], sPA[tt * PAD + t],
                         sPP[tt * PAD + t], A, L, H);
        __syncthreads();
    }

    // publish aggregate
    d_A[c * Bn + b] = A;
    d_L[c * Bn + b] = L;
    d_H[c * Bn + b] = H;
    __threadfence();
    __syncthreads();
    if (t == 0) atomicExch(&d_flag[c * NRG + rg], 1);

    // prefetch phase-B slice 0 while lookback resolves
    stage_slice(g_ga, base, tq, rophase, sGA);
    stage_slice(g_pa, base, tq, rophase, sPA);
    stage_slice(g_pp, base, tq, rophase, sPP);
    stage_slice(g_pr, base, tq, rophase, sPR);

    // ── Lookback: derive chunk-start state s0 ───────────────────────────
    float s0;
    if (c == 0) {
        s0 = 6.75f;
    } else {
        float aA = 0.0f, aL = -3.4e38f, aH = 3.4e38f;   // identity
        int p = c - 1;
        for (;;) {
            if (t == 0) {
                int f;
                do {
                    f = atomicAdd(&d_flag[p * NRG + rg], 0);
                    if (f == 0) __nanosleep(64);
                } while (f == 0);
                s_flag = f;
            }
            __syncthreads();
            const int f = s_flag;
            __syncthreads();
            if (f == 2) {
                const float sp = __ldcg(&d_S[p * Bn + b]);
                s0 = fminf(fmaxf(sp + aA, aL), aH);
                break;
            }
            const float a1 = __ldcg(&d_A[p * Bn + b]);
            const float l1 = __ldcg(&d_L[p * Bn + b]);
            const float h1 = __ldcg(&d_H[p * Bn + b]);
            const float nl = fmaxf(l1 + aA, aL);         // acc ∘ F_p
            const float nh = fminf(fmaxf(h1 + aA, aL), aH);
            aA = a1 + aA;
            aL = nl; aH = nh;
            if (--p < 0) {
                s0 = fminf(fmaxf(6.75f + aA, aL), aH);
                break;
            }
        }
    }

    // publish inclusive end-state of this chunk
    d_S[c * Bn + b] = fminf(fmaxf(s0 + A, L), H);
    __threadfence();
    __syncthreads();
    if (t == 0) atomicExch(&d_flag[c * NRG + rg], 2);

    // ── Phase B: replay chunk, all I/O coalesced via smem ───────────────
    float s = s0;
    if (c == 0) g_trace[(size_t)b * (Tn + 1)] = 6.75f;

    for (int sl = 0; sl < NSL; ++sl) {
        if (sl > 0) {   // slice 0 was prefetched above
            const size_t soff = base + sl * SL;
            stage_slice(g_ga, soff, tq, rophase, sGA);
            stage_slice(g_pa, soff, tq, rophase, sPA);
            stage_slice(g_pp, soff, tq, rophase, sPP);
            stage_slice(g_pr, soff, tq, rophase, sPR);
        }
        __syncthreads();

        // scan 16 steps; write trace into sGA, cost into sPR (in place)
#pragma unroll
        for (int tt = 0; tt < SL; ++tt) {
            float cost, tr;
            s = battery_step(s, sGA[tt * PAD + t], sPA[tt * PAD + t],
                             sPP[tt * PAD + t], sPR[tt * PAD + t], cost, tr);
            sGA[tt * PAD + t] = tr;
            sPR[tt * PAD + t] = cost;
        }
        __syncthreads();

        // flush: warp w owns rows [w*32, w*32+32); 2 rows per iteration
        const int tcol = c * Tc + sl * SL;
#pragma unroll
        for (int rr = 0; rr < 32; rr += 2) {
            const int r = w * 32 + rr + rh;
            const float trv = sGA[l16 * PAD + r];
            const float cov = sPR[l16 * PAD + r];
            g_trace[(size_t)(b0 + r) * (Tn + 1) + tcol + 1 + l16] = trv;
            g_cost [(size_t)(b0 + r) * Tn       + tcol + l16]     = cov;
        }
        __syncthreads();
    }
}

extern "C" void kernel_launch(void* const* d_in, const int* in_sizes, int n_in,
                              void* d_out, int out_size)
{
    const float* ga = (const float*)d_in[0];
    const float* pa = (const float*)d_in[1];
    const float* pp = (const float*)d_in[2];
    const float* pr = (const float*)d_in[3];

    float* out   = (float*)d_out;
    float* trace = out;                               // [B, T+1]
    float* cost  = out + (size_t)Bn * (Tn + 1);       // [B, T]

    reset_flags_kernel<<<(NC * NRG + 255) / 256, 256>>>();
    fused_kernel<<<NC * NRG, RPB>>>(ga, pa, pp, pr, trace, cost);
}

// round 9
// speedup vs baseline: 2.3404x; 1.2720x over previous
#include <cuda_runtime.h>
#include <cuda_bf16.h>

constexpr int Bn  = 4096;
constexpr int Tn  = 4096;
constexpr int NC  = 256;          // chunks per row
constexpr int Tc  = Tn / NC;      // 16 steps per chunk (== one slice)
constexpr int SL  = 16;           // steps per slice
constexpr int RPB = 128;          // rows per block (= threads per block)
constexpr int PAD = 130;          // smem row stride in words
constexpr int NRG = Bn / RPB;     // 32 row-groups

__device__ float d_A[NC * Bn];    // chunk aggregate: shift
__device__ float d_L[NC * Bn];    // chunk aggregate: lower clamp
__device__ float d_H[NC * Bn];    // chunk aggregate: upper clamp
__device__ float d_S[NC * Bn];    // chunk END state (inclusive)
__device__ int   d_flag[NC * NRG];// 0 = none, 1 = aggregate, 2 = inclusive

// step map as clamp: s -> min(max(s + a, L), H)
__device__ __forceinline__ void compose_step(
    float ga, float pa, float pp, float& A, float& L, float& H)
{
    const float K  = 5.0f / 60.0f;
    const float RK = 5.0f * K;

    float p   = fminf(fmaxf(pa * pp, 0.0f), 5.0f) * K;
    float glK = fmaxf(ga * 5.0f, -5.0f) * K;
    float a   = fminf(p + glK, RK);
    float h   = 13.5f + fminf(glK, 0.0f);

    A = A + a;
    L = fmaxf(L + a, 0.0f);
    H = fminf(fmaxf(H + a, 0.0f), h);
}

__device__ __forceinline__ float battery_step(
    float s, float ga, float pa, float pp, float pr,
    float& cost_out, float& trace_out)
{
    const float C = 13.5f;
    const float K = 5.0f / 60.0f;
    const float R = 5.0f;

    float rp  = fminf(fmaxf(pa * pp, 0.0f), R);
    float p   = rp * K;
    float gl  = fmaxf(ga * R, -R);
    float pvk = pp * K;
    float prc = pr * 1.0e-3f;

    float after_pv = fminf(s + p, C);
    float amt      = after_pv - s;
    float hi       = R - amt * 12.0f;
    float rgr      = fminf(gl, hi);
    float ns       = fminf(fmaxf(after_pv + rgr * K, 0.0f), C);

    float grid_amt  = ns - after_pv;
    float pv_export = amt - pvk;
    cost_out  = prc * (grid_amt + pv_export);
    trace_out = ns;
    return ns;
}

// stage one array's [128 rows x 64B] chunk into time-major smem [SL][PAD]
// streaming loads: inputs are read exactly once chip-wide
__device__ __forceinline__ void stage_chunk(
    const float* __restrict__ g, size_t chunk_base, int tq, int rophase,
    float* __restrict__ sm)
{
#pragma unroll
    for (int p = 0; p < 4; ++p) {
        const int row = p * 32 + rophase;
        const float4 v = __ldcs(reinterpret_cast<const float4*>(
            g + chunk_base + (size_t)row * Tn + tq * 4));
        sm[(tq * 4 + 0) * PAD + row] = v.x;
        sm[(tq * 4 + 1) * PAD + row] = v.y;
        sm[(tq * 4 + 2) * PAD + row] = v.z;
        sm[(tq * 4 + 3) * PAD + row] = v.w;
    }
}

__global__ void __launch_bounds__(256) reset_flags_kernel()
{
    const int i = blockIdx.x * 256 + threadIdx.x;
    if (i < NC * NRG) d_flag[i] = 0;
}

__global__ void __launch_bounds__(RPB) fused_kernel(
    const float* __restrict__ g_ga, const float* __restrict__ g_pa,
    const float* __restrict__ g_pp, const float* __restrict__ g_pr,
    float* __restrict__ g_trace, float* __restrict__ g_cost)
{
    __shared__ float sGA[SL * PAD], sPA[SL * PAD], sPP[SL * PAD], sPR[SL * PAD];
    __shared__ int s_flag;

    const int t  = threadIdx.x;
    const int rg = blockIdx.x & (NRG - 1);
    const int c  = blockIdx.x >> 5;
    const int b0 = rg * RPB;
    const int b  = b0 + t;

    const int tq      = t & 3;
    const int rophase = t >> 2;
    const int w       = t >> 5;
    const int lane    = t & 31;
    const int l16     = lane & 15;
    const int rh      = lane >> 4;

    const size_t base = (size_t)b0 * Tn + (size_t)c * Tc;

    // ── Stage: entire chunk of all 4 arrays, one 16-load burst ──────────
    stage_chunk(g_ga, base, tq, rophase, sGA);
    stage_chunk(g_pa, base, tq, rophase, sPA);
    stage_chunk(g_pp, base, tq, rophase, sPP);
    stage_chunk(g_pr, base, tq, rophase, sPR);
    __syncthreads();

    // ── Phase A: compose chunk clamp function from smem ─────────────────
    float A = 0.0f, L = 0.0f, H = 13.5f;   // identity on [0, C]
#pragma unroll
    for (int tt = 0; tt < SL; ++tt)
        compose_step(sGA[tt * PAD + t], sPA[tt * PAD + t],
                     sPP[tt * PAD + t], A, L, H);

    d_A[c * Bn + b] = A;
    d_L[c * Bn + b] = L;
    d_H[c * Bn + b] = H;
    __threadfence();
    __syncthreads();
    if (t == 0) atomicExch(&d_flag[c * NRG + rg], 1);

    // ── Lookback: derive chunk-start state s0 ───────────────────────────
    float s0;
    if (c == 0) {
        s0 = 6.75f;
    } else {
        float aA = 0.0f, aL = -3.4e38f, aH = 3.4e38f;   // identity
        int p = c - 1;
        for (;;) {
            if (t == 0) {
                int f;
                do {
                    f = atomicAdd(&d_flag[p * NRG + rg], 0);
                    if (f == 0) __nanosleep(64);
                } while (f == 0);
                s_flag = f;
            }
            __syncthreads();
            const int f = s_flag;
            __syncthreads();
            if (f == 2) {
                const float sp = __ldcg(&d_S[p * Bn + b]);
                s0 = fminf(fmaxf(sp + aA, aL), aH);
                break;
            }
            const float a1 = __ldcg(&d_A[p * Bn + b]);
            const float l1 = __ldcg(&d_L[p * Bn + b]);
            const float h1 = __ldcg(&d_H[p * Bn + b]);
            const float nl = fmaxf(l1 + aA, aL);         // acc ∘ F_p
            const float nh = fminf(fmaxf(h1 + aA, aL), aH);
            aA = a1 + aA;
            aL = nl; aH = nh;
            if (--p < 0) {
                s0 = fminf(fmaxf(6.75f + aA, aL), aH);
                break;
            }
        }
    }

    // publish inclusive end-state of this chunk
    d_S[c * Bn + b] = fminf(fmaxf(s0 + A, L), H);
    __threadfence();
    __syncthreads();
    if (t == 0) atomicExch(&d_flag[c * NRG + rg], 2);

    // ── Phase B: replay chunk from smem (no re-read from DRAM) ──────────
    float s = s0;
    if (c == 0) g_trace[(size_t)b * (Tn + 1)] = 6.75f;

#pragma unroll
    for (int tt = 0; tt < SL; ++tt) {
        float cost, tr;
        s = battery_step(s, sGA[tt * PAD + t], sPA[tt * PAD + t],
                         sPP[tt * PAD + t], sPR[tt * PAD + t], cost, tr);
        sGA[tt * PAD + t] = tr;      // trace in place
        sPR[tt * PAD + t] = cost;    // cost in place
    }
    __syncthreads();

    // ── Flush: coalesced streaming stores, 2 rows per iteration ─────────
    const int tcol = c * Tc;
#pragma unroll
    for (int rr = 0; rr < 32; rr += 2) {
        const int r = w * 32 + rr + rh;
        const float trv = sGA[l16 * PAD + r];
        const float cov = sPR[l16 * PAD + r];
        __stcs(&g_trace[(size_t)(b0 + r) * (Tn + 1) + tcol + 1 + l16], trv);
        __stcs(&g_cost [(size_t)(b0 + r) * Tn       + tcol + l16],     cov);
    }
}

extern "C" void kernel_launch(void* const* d_in, const int* in_sizes, int n_in,
                              void* d_out, int out_size)
{
    const float* ga = (const float*)d_in[0];
    const float* pa = (const float*)d_in[1];
    const float* pp = (const float*)d_in[2];
    const float* pr = (const float*)d_in[3];

    float* out   = (float*)d_out;
    float* trace = out;                               // [B, T+1]
    float* cost  = out + (size_t)Bn * (Tn + 1);       // [B, T]

    reset_flags_kernel<<<(NC * NRG + 255) / 256, 256>>>();
    fused_kernel<<<NC * NRG, RPB>>>(ga, pa, pp, pr, trace, cost);
}

// round 12
// speedup vs baseline: 2.6584x; 1.1359x over previous
#include <cuda_runtime.h>
#include <cuda_bf16.h>

constexpr int Bn  = 4096;
constexpr int Tn  = 4096;
constexpr int NC  = 256;          // chunks per row
constexpr int Tc  = Tn / NC;      // 16 steps per chunk
constexpr int SL  = 16;           // steps per slice (== chunk)
constexpr int RPB = 128;          // rows per block (= threads per block)
constexpr int PAD = 130;          // smem row stride in words
constexpr int NRG = Bn / RPB;     // 32 row-groups

__device__ float4 d_ALH[NC * Bn]; // chunk aggregate: (shift, lo, hi, unused)
__device__ float  d_S[NC * Bn];   // chunk END state (inclusive)
__device__ int    d_flag[NC * NRG];// 0 none, 1 aggregate, 2 inclusive

// step map as clamp: s -> min(max(s + a, L), H)
__device__ __forceinline__ void compose_step(
    float ga, float pa, float pp, float& A, float& L, float& H)
{
    const float K  = 5.0f / 60.0f;
    const float RK = 5.0f * K;

    float p   = fminf(fmaxf(pa * pp, 0.0f), 5.0f) * K;
    float glK = fmaxf(ga * 5.0f, -5.0f) * K;
    float a   = fminf(p + glK, RK);
    float h   = 13.5f + fminf(glK, 0.0f);

    A = A + a;
    L = fmaxf(L + a, 0.0f);
    H = fminf(fmaxf(H + a, 0.0f), h);
}

__device__ __forceinline__ float battery_step(
    float s, float ga, float pa, float pp, float pr,
    float& cost_out, float& trace_out)
{
    const float C = 13.5f;
    const float K = 5.0f / 60.0f;
    const float R = 5.0f;

    float rp  = fminf(fmaxf(pa * pp, 0.0f), R);
    float p   = rp * K;
    float gl  = fmaxf(ga * R, -R);
    float pvk = pp * K;
    float prc = pr * 1.0e-3f;

    float after_pv = fminf(s + p, C);
    float amt      = after_pv - s;
    float hi       = R - amt * 12.0f;
    float rgr      = fminf(gl, hi);
    float ns       = fminf(fmaxf(after_pv + rgr * K, 0.0f), C);

    float grid_amt  = ns - after_pv;
    float pv_export = amt - pvk;
    cost_out  = prc * (grid_amt + pv_export);
    trace_out = ns;
    return ns;
}

// stage one array's [128 rows x 64B] chunk into time-major smem [SL][PAD]
__device__ __forceinline__ void stage_chunk(
    const float* __restrict__ g, size_t chunk_base, int tq, int rophase,
    float* __restrict__ sm)
{
#pragma unroll
    for (int p = 0; p < 4; ++p) {
        const int row = p * 32 + rophase;
        const float4 v = __ldcs(reinterpret_cast<const float4*>(
            g + chunk_base + (size_t)row * Tn + tq * 4));
        sm[(tq * 4 + 0) * PAD + row] = v.x;
        sm[(tq * 4 + 1) * PAD + row] = v.y;
        sm[(tq * 4 + 2) * PAD + row] = v.z;
        sm[(tq * 4 + 3) * PAD + row] = v.w;
    }
}

__global__ void __launch_bounds__(256) reset_flags_kernel()
{
    const int i = blockIdx.x * 256 + threadIdx.x;
    if (i < NC * NRG) d_flag[i] = 0;
}

__global__ void __launch_bounds__(RPB, 6) fused_kernel(
    const float* __restrict__ g_ga, const float* __restrict__ g_pa,
    const float* __restrict__ g_pp, const float* __restrict__ g_pr,
    float* __restrict__ g_trace, float* __restrict__ g_cost)
{
    __shared__ float sGA[SL * PAD], sPA[SL * PAD], sPP[SL * PAD], sPR[SL * PAD];
    __shared__ int s_wd, s_wt;

    const int t  = threadIdx.x;
    const int rg = blockIdx.x & (NRG - 1);
    const int c  = blockIdx.x >> 5;
    const int b0 = rg * RPB;
    const int b  = b0 + t;

    const int tq      = t & 3;
    const int rophase = t >> 2;
    const int w       = t >> 5;
    const int lane    = t & 31;
    const int l16     = lane & 15;
    const int rh      = lane >> 4;

    const size_t base = (size_t)b0 * Tn + (size_t)c * Tc;

    // ── Issue price loads early; scatter later (hidden under lookback) ──
    float4 vpr[4];
#pragma unroll
    for (int p = 0; p < 4; ++p) {
        const int row = p * 32 + rophase;
        vpr[p] = __ldcs(reinterpret_cast<const float4*>(
            g_pr + base + (size_t)row * Tn + tq * 4));
    }

    // ── Stage ga/pa/pp and compose chunk clamp function ─────────────────
    stage_chunk(g_ga, base, tq, rophase, sGA);
    stage_chunk(g_pa, base, tq, rophase, sPA);
    stage_chunk(g_pp, base, tq, rophase, sPP);
    __syncthreads();

    float A = 0.0f, L = 0.0f, H = 13.5f;   // identity on [0, C]
#pragma unroll
    for (int tt = 0; tt < SL; ++tt)
        compose_step(sGA[tt * PAD + t], sPA[tt * PAD + t],
                     sPP[tt * PAD + t], A, L, H);

    d_ALH[(size_t)c * Bn + b] = make_float4(A, L, H, 0.0f);
    __threadfence();
    __syncthreads();
    if (t == 0) atomicExch(&d_flag[c * NRG + rg], 1);

    // ── Windowed warp-parallel lookback ─────────────────────────────────
    float s0 = 6.75f;
    if (c != 0) {
        float aA = 0.0f, aL = -3.4e38f, aH = 3.4e38f;   // identity
        int cc = c;
        for (;;) {
            __syncthreads();
            if (w == 0) {
                int wd = 0, wt = 2;
                for (;;) {
                    const int p = cc - 1 - lane;
                    int v = 2;
                    if (p >= 0) v = __ldcg(&d_flag[p * NRG + rg]);
                    const unsigned m2 = __ballot_sync(0xffffffffu, v == 2);
                    const unsigned m1 = __ballot_sync(0xffffffffu, v >= 1);
                    if (m2) {
                        const int l2 = __ffs(m2) - 1;
                        const unsigned need = (l2 == 0) ? 0u : ((1u << l2) - 1u);
                        if ((m1 & need) == need) {
                            wd = l2;
                            wt = (cc - 1 - l2 < 0) ? 1 : 0;  // 1 = hit initial state
                            break;
                        }
                    } else if (m1 == 0xffffffffu) {
                        wd = 32; wt = 2;                     // slide window deeper
                        break;
                    }
                    __nanosleep(50);
                }
                if (lane == 0) { s_wd = wd; s_wt = wt; }
            }
            __syncthreads();
            const int wd = s_wd;
            const int wt = s_wt;

            // every thread composes its own row's aggregates, newest first
            for (int l = 0; l < wd; ++l) {
                const float4 f = __ldcg(&d_ALH[(size_t)(cc - 1 - l) * Bn + b]);
                const float nl = fmaxf(f.y + aA, aL);        // acc ∘ F_p
                const float nh = fminf(fmaxf(f.z + aA, aL), aH);
                aA += f.x;
                aL = nl; aH = nh;
            }
            if (wt == 0) {
                const float sp = __ldcg(&d_S[(size_t)(cc - 1 - wd) * Bn + b]);
                s0 = fminf(fmaxf(sp + aA, aL), aH);
                break;
            }
            if (wt == 1) {
                s0 = fminf(fmaxf(6.75f + aA, aL), aH);
                break;
            }
            cc -= 32;
        }
    }

    // scatter prefetched price tile (overlapped with lookback latency)
#pragma unroll
    for (int p = 0; p < 4; ++p) {
        const int row = p * 32 + rophase;
        sPR[(tq * 4 + 0) * PAD + row] = vpr[p].x;
        sPR[(tq * 4 + 1) * PAD + row] = vpr[p].y;
        sPR[(tq * 4 + 2) * PAD + row] = vpr[p].z;
        sPR[(tq * 4 + 3) * PAD + row] = vpr[p].w;
    }

    // publish inclusive end-state of this chunk
    d_S[(size_t)c * Bn + b] = fminf(fmaxf(s0 + A, L), H);
    __threadfence();
    __syncthreads();
    if (t == 0) atomicExch(&d_flag[c * NRG + rg], 2);

    // ── Replay chunk from smem (no DRAM re-read) ────────────────────────
    float s = s0;
    if (c == 0) g_trace[(size_t)b * (Tn + 1)] = 6.75f;

#pragma unroll
    for (int tt = 0; tt < SL; ++tt) {
        float cost, tr;
        s = battery_step(s, sGA[tt * PAD + t], sPA[tt * PAD + t],
                         sPP[tt * PAD + t], sPR[tt * PAD + t], cost, tr);
        sGA[tt * PAD + t] = tr;      // trace in place
        sPR[tt * PAD + t] = cost;    // cost in place
    }
    __syncthreads();

    // ── Flush: coalesced streaming stores, 2 rows per iteration ─────────
    const int tcol = c * Tc;
#pragma unroll
    for (int rr = 0; rr < 32; rr += 2) {
        const int r = w * 32 + rr + rh;
        const float trv = sGA[l16 * PAD + r];
        const float cov = sPR[l16 * PAD + r];
        __stcs(&g_trace[(size_t)(b0 + r) * (Tn + 1) + tcol + 1 + l16], trv);
        __stcs(&g_cost [(size_t)(b0 + r) * Tn       + tcol + l16],     cov);
    }
}

extern "C" void kernel_launch(void* const* d_in, const int* in_sizes, int n_in,
                              void* d_out, int out_size)
{
    const float* ga = (const float*)d_in[0];
    const float* pa = (const float*)d_in[1];
    const float* pp = (const float*)d_in[2];
    const float* pr = (const float*)d_in[3];

    float* out   = (float*)d_out;
    float* trace = out;                               // [B, T+1]
    float* cost  = out + (size_t)Bn * (Tn + 1);       // [B, T]

    reset_flags_kernel<<<(NC * NRG + 255) / 256, 256>>>();
    fused_kernel<<<NC * NRG, RPB>>>(ga, pa, pp, pr, trace, cost);
}